// round 1
// baseline (speedup 1.0000x reference)
#include <cuda_runtime.h>

#define HIDDEN    1024
#define MOE_FF    512
#define SHARED_FF 2816
#define NE        16
#define NTOK      2048
#define NENT      (2*NTOK)

// ---------------- scratch (device globals; no allocation allowed) ----------
__device__ float g_H1[NTOK * SHARED_FF];     // shared-expert hidden  (23 MB)
__device__ float g_Hx[NENT * MOE_FF];        // expert hidden per entry (8 MB)
__device__ float g_partial[NENT * HIDDEN];   // weighted expert out per entry (16 MB)
__device__ int   g_list[NE][NTOK];           // entry id (2n+k) per expert bucket
__device__ int   g_cnt[NE];
__device__ float g_wts[NENT];                // renormalized router weight per entry
__device__ float g_sig[NTOK];                // shared-expert sigmoid gate

__device__ __forceinline__ float silu_f(float v) { return v / (1.f + __expf(-v)); }

// ---------------- misc ------------------------------------------------------
__global__ void k_zero_cnt() {
    if (threadIdx.x < NE) g_cnt[threadIdx.x] = 0;
}

// ---------------- router: logits -> top2 -> renorm weights + buckets --------
// one block (128 thr) per token. NORM_TOPK makes the softmax denominator
// cancel: w_k = exp(l_k - lmax) / sum_over_top2.
__global__ void k_router(const float* __restrict__ x,
                         const float* __restrict__ gw,
                         const float* __restrict__ sgw) {
    int n = blockIdx.x;
    int t = threadIdx.x;
    float xv[8];
#pragma unroll
    for (int i = 0; i < 8; i++) xv[i] = x[n * HIDDEN + t + i * 128];

    __shared__ float red[17 * 4];
    for (int e = 0; e < 17; e++) {
        const float* wr = (e < 16) ? (gw + e * HIDDEN) : sgw;
        float s = 0.f;
#pragma unroll
        for (int i = 0; i < 8; i++) s += xv[i] * wr[t + i * 128];
#pragma unroll
        for (int o = 16; o; o >>= 1) s += __shfl_xor_sync(0xffffffffu, s, o);
        if ((t & 31) == 0) red[e * 4 + (t >> 5)] = s;
    }
    __syncthreads();
    if (t == 0) {
        float lg[17];
        for (int e = 0; e < 17; e++)
            lg[e] = red[e * 4] + red[e * 4 + 1] + red[e * 4 + 2] + red[e * 4 + 3];
        int i0 = 0;
        for (int e = 1; e < 16; e++) if (lg[e] > lg[i0]) i0 = e;
        int i1 = -1;
        for (int e = 0; e < 16; e++) {
            if (e == i0) continue;
            if (i1 < 0 || lg[e] > lg[i1]) i1 = e;
        }
        float m  = lg[i0];
        float e0 = expf(lg[i0] - m);
        float e1 = expf(lg[i1] - m);
        float inv = 1.f / (e0 + e1);
        g_wts[2 * n]     = e0 * inv;
        g_wts[2 * n + 1] = e1 * inv;
        int p0 = atomicAdd(&g_cnt[i0], 1); g_list[i0][p0] = 2 * n;
        int p1 = atomicAdd(&g_cnt[i1], 1); g_list[i1][p1] = 2 * n + 1;
        g_sig[n] = 1.f / (1.f + expf(-lg[16]));
    }
}

// ---------------- GEMM tiles: BM=BN=64, BK=16, 256 thr, 4x4 microtile -------

// shared expert gemm1: H1 = silu(X @ Wg^T) * (X @ Wu^T)
// X [2048,1024] row-major, Wg/Wu [2816,1024] row-major (both K-inner: "NT")
__global__ void k_shared_gemm1(const float* __restrict__ X,
                               const float* __restrict__ Wg,
                               const float* __restrict__ Wu) {
    __shared__ float As[16][64], Bgs[16][64], Bus[16][64];
    const int bm = blockIdx.y * 64, bn = blockIdx.x * 64;
    const int t = threadIdx.x;
    const int tx = t & 15, ty = t >> 4;
    const int lr = t >> 2, lq = t & 3;
    float cg[4][4], cu[4][4];
#pragma unroll
    for (int i = 0; i < 4; i++)
#pragma unroll
        for (int j = 0; j < 4; j++) { cg[i][j] = 0.f; cu[i][j] = 0.f; }

    const float* Ap = X  + (size_t)(bm + lr) * HIDDEN + lq * 4;
    const float* Gp = Wg + (size_t)(bn + lr) * HIDDEN + lq * 4;
    const float* Up = Wu + (size_t)(bn + lr) * HIDDEN + lq * 4;

    for (int k0 = 0; k0 < HIDDEN; k0 += 16) {
        float4 a4 = *(const float4*)(Ap + k0);
        float4 g4 = *(const float4*)(Gp + k0);
        float4 u4 = *(const float4*)(Up + k0);
        As [lq * 4 + 0][lr] = a4.x; As [lq * 4 + 1][lr] = a4.y;
        As [lq * 4 + 2][lr] = a4.z; As [lq * 4 + 3][lr] = a4.w;
        Bgs[lq * 4 + 0][lr] = g4.x; Bgs[lq * 4 + 1][lr] = g4.y;
        Bgs[lq * 4 + 2][lr] = g4.z; Bgs[lq * 4 + 3][lr] = g4.w;
        Bus[lq * 4 + 0][lr] = u4.x; Bus[lq * 4 + 1][lr] = u4.y;
        Bus[lq * 4 + 2][lr] = u4.z; Bus[lq * 4 + 3][lr] = u4.w;
        __syncthreads();
#pragma unroll
        for (int kk = 0; kk < 16; kk++) {
            float4 av = *(const float4*)&As [kk][ty * 4];
            float4 gv = *(const float4*)&Bgs[kk][tx * 4];
            float4 uv = *(const float4*)&Bus[kk][tx * 4];
            float a[4] = {av.x, av.y, av.z, av.w};
            float g[4] = {gv.x, gv.y, gv.z, gv.w};
            float u[4] = {uv.x, uv.y, uv.z, uv.w};
#pragma unroll
            for (int i = 0; i < 4; i++)
#pragma unroll
                for (int j = 0; j < 4; j++) {
                    cg[i][j] += a[i] * g[j];
                    cu[i][j] += a[i] * u[j];
                }
        }
        __syncthreads();
    }
#pragma unroll
    for (int i = 0; i < 4; i++) {
        int row = bm + ty * 4 + i;
        float* op = g_H1 + (size_t)row * SHARED_FF + bn + tx * 4;
#pragma unroll
        for (int j = 0; j < 4; j++) op[j] = silu_f(cg[i][j]) * cu[i][j];
    }
}

// shared expert gemm2: out = (H1 @ Wd^T) * sigmoid_gate   (NT, K=2816)
__global__ void k_shared_gemm2(const float* __restrict__ Wd, float* __restrict__ out) {
    __shared__ float As[16][64], Bs[16][64];
    const int bm = blockIdx.y * 64, bn = blockIdx.x * 64;
    const int t = threadIdx.x;
    const int tx = t & 15, ty = t >> 4;
    const int lr = t >> 2, lq = t & 3;
    float c[4][4];
#pragma unroll
    for (int i = 0; i < 4; i++)
#pragma unroll
        for (int j = 0; j < 4; j++) c[i][j] = 0.f;

    const float* Ap = g_H1 + (size_t)(bm + lr) * SHARED_FF + lq * 4;
    const float* Bp = Wd   + (size_t)(bn + lr) * SHARED_FF + lq * 4;

    for (int k0 = 0; k0 < SHARED_FF; k0 += 16) {
        float4 a4 = *(const float4*)(Ap + k0);
        float4 b4 = *(const float4*)(Bp + k0);
        As[lq * 4 + 0][lr] = a4.x; As[lq * 4 + 1][lr] = a4.y;
        As[lq * 4 + 2][lr] = a4.z; As[lq * 4 + 3][lr] = a4.w;
        Bs[lq * 4 + 0][lr] = b4.x; Bs[lq * 4 + 1][lr] = b4.y;
        Bs[lq * 4 + 2][lr] = b4.z; Bs[lq * 4 + 3][lr] = b4.w;
        __syncthreads();
#pragma unroll
        for (int kk = 0; kk < 16; kk++) {
            float4 av = *(const float4*)&As[kk][ty * 4];
            float4 bv = *(const float4*)&Bs[kk][tx * 4];
            float a[4] = {av.x, av.y, av.z, av.w};
            float b[4] = {bv.x, bv.y, bv.z, bv.w};
#pragma unroll
            for (int i = 0; i < 4; i++)
#pragma unroll
                for (int j = 0; j < 4; j++) c[i][j] += a[i] * b[j];
        }
        __syncthreads();
    }
#pragma unroll
    for (int i = 0; i < 4; i++) {
        int row = bm + ty * 4 + i;
        float s = g_sig[row];
        float* op = out + (size_t)row * HIDDEN + bn + tx * 4;
#pragma unroll
        for (int j = 0; j < 4; j++) op[j] = c[i][j] * s;
    }
}

// expert gemm1: for bucket e, Hx[entry] = silu(x_tok @ Wg_e) * (x_tok @ Wu_e)
// Wgu[e] is [K=1024][2*MOE_FF] (N-inner: "NN"). Gate cols [0,512), up [512,1024).
__global__ void k_expert_gemm1(const float* __restrict__ X,
                               const float* __restrict__ Wgu) {
    const int e = blockIdx.z;
    const int Me = g_cnt[e];
    const int bm = blockIdx.y * 64;
    if (bm >= Me) return;
    const int bn = blockIdx.x * 64;   // moe_ff column

    __shared__ float As[16][64], Bgs[16][64], Bus[16][64];
    const int t = threadIdx.x;
    const int tx = t & 15, ty = t >> 4;
    const int lr = t >> 2, lq = t & 3;
    const int kr = t >> 4, nq = t & 15;

    float cg[4][4], cu[4][4];
#pragma unroll
    for (int i = 0; i < 4; i++)
#pragma unroll
        for (int j = 0; j < 4; j++) { cg[i][j] = 0.f; cu[i][j] = 0.f; }

    int mload = bm + lr; if (mload > Me - 1) mload = Me - 1;
    const int tok = g_list[e][mload] >> 1;
    const float* Ap = X + (size_t)tok * HIDDEN + lq * 4;
    const float* Bb = Wgu + (size_t)e * HIDDEN * 2 * MOE_FF;

    for (int k0 = 0; k0 < HIDDEN; k0 += 16) {
        float4 a4 = *(const float4*)(Ap + k0);
        As[lq * 4 + 0][lr] = a4.x; As[lq * 4 + 1][lr] = a4.y;
        As[lq * 4 + 2][lr] = a4.z; As[lq * 4 + 3][lr] = a4.w;
        const float* brow = Bb + (size_t)(k0 + kr) * (2 * MOE_FF);
        *(float4*)&Bgs[kr][nq * 4] = *(const float4*)(brow + bn + nq * 4);
        *(float4*)&Bus[kr][nq * 4] = *(const float4*)(brow + MOE_FF + bn + nq * 4);
        __syncthreads();
#pragma unroll
        for (int kk = 0; kk < 16; kk++) {
            float4 av = *(const float4*)&As [kk][ty * 4];
            float4 gv = *(const float4*)&Bgs[kk][tx * 4];
            float4 uv = *(const float4*)&Bus[kk][tx * 4];
            float a[4] = {av.x, av.y, av.z, av.w};
            float g[4] = {gv.x, gv.y, gv.z, gv.w};
            float u[4] = {uv.x, uv.y, uv.z, uv.w};
#pragma unroll
            for (int i = 0; i < 4; i++)
#pragma unroll
                for (int j = 0; j < 4; j++) {
                    cg[i][j] += a[i] * g[j];
                    cu[i][j] += a[i] * u[j];
                }
        }
        __syncthreads();
    }
#pragma unroll
    for (int i = 0; i < 4; i++) {
        int m2 = bm + ty * 4 + i;
        if (m2 < Me) {
            int ent = g_list[e][m2];
            float* op = g_Hx + (size_t)ent * MOE_FF + bn + tx * 4;
#pragma unroll
            for (int j = 0; j < 4; j++) op[j] = silu_f(cg[i][j]) * cu[i][j];
        }
    }
}

// expert gemm2: partial[entry] = (Hx[entry] @ Wd_e) * router_weight
// Wd[e] is [K=512][N=1024] ("NN").
__global__ void k_expert_gemm2(const float* __restrict__ Wd) {
    const int e = blockIdx.z;
    const int Me = g_cnt[e];
    const int bm = blockIdx.y * 64;
    if (bm >= Me) return;
    const int bn = blockIdx.x * 64;

    __shared__ float As[16][64], Bs[16][64];
    const int t = threadIdx.x;
    const int tx = t & 15, ty = t >> 4;
    const int lr = t >> 2, lq = t & 3;
    const int kr = t >> 4, nq = t & 15;

    float c[4][4];
#pragma unroll
    for (int i = 0; i < 4; i++)
#pragma unroll
        for (int j = 0; j < 4; j++) c[i][j] = 0.f;

    int mload = bm + lr; if (mload > Me - 1) mload = Me - 1;
    const int ent_l = g_list[e][mload];
    const float* Ap = g_Hx + (size_t)ent_l * MOE_FF + lq * 4;
    const float* Bb = Wd + (size_t)e * MOE_FF * HIDDEN;

    for (int k0 = 0; k0 < MOE_FF; k0 += 16) {
        float4 a4 = *(const float4*)(Ap + k0);
        As[lq * 4 + 0][lr] = a4.x; As[lq * 4 + 1][lr] = a4.y;
        As[lq * 4 + 2][lr] = a4.z; As[lq * 4 + 3][lr] = a4.w;
        *(float4*)&Bs[kr][nq * 4] =
            *(const float4*)(Bb + (size_t)(k0 + kr) * HIDDEN + bn + nq * 4);
        __syncthreads();
#pragma unroll
        for (int kk = 0; kk < 16; kk++) {
            float4 av = *(const float4*)&As[kk][ty * 4];
            float4 bv = *(const float4*)&Bs[kk][tx * 4];
            float a[4] = {av.x, av.y, av.z, av.w};
            float b[4] = {bv.x, bv.y, bv.z, bv.w};
#pragma unroll
            for (int i = 0; i < 4; i++)
#pragma unroll
                for (int j = 0; j < 4; j++) c[i][j] += a[i] * b[j];
        }
        __syncthreads();
    }
#pragma unroll
    for (int i = 0; i < 4; i++) {
        int m2 = bm + ty * 4 + i;
        if (m2 < Me) {
            int ent = g_list[e][m2];
            float w = g_wts[ent];
            float* op = g_partial + (size_t)ent * HIDDEN + bn + tx * 4;
#pragma unroll
            for (int j = 0; j < 4; j++) op[j] = c[i][j] * w;
        }
    }
}

// out += partial[2n] + partial[2n+1]   (out already holds shared-expert term)
__global__ void k_combine(float* __restrict__ out) {
    int idx = blockIdx.x * blockDim.x + threadIdx.x;   // float4 index
    const int W = HIDDEN / 4;
    int n = idx / W;
    int c = idx - n * W;
    float4* o = (float4*)out;
    const float4* p = (const float4*)g_partial;
    float4 v  = o[idx];
    float4 p0 = p[(size_t)(2 * n) * W + c];
    float4 p1 = p[(size_t)(2 * n + 1) * W + c];
    v.x += p0.x + p1.x; v.y += p0.y + p1.y;
    v.z += p0.z + p1.z; v.w += p0.w + p1.w;
    o[idx] = v;
}

// ---------------- launch ----------------------------------------------------
extern "C" void kernel_launch(void* const* d_in, const int* in_sizes, int n_in,
                              void* d_out, int out_size) {
    const float* x    = (const float*)d_in[0];
    const float* gw   = (const float*)d_in[1];
    const float* wgu  = (const float*)d_in[2];
    const float* wdn  = (const float*)d_in[3];
    const float* swg  = (const float*)d_in[4];
    const float* swu  = (const float*)d_in[5];
    const float* swd  = (const float*)d_in[6];
    const float* sgw  = (const float*)d_in[7];
    float* out = (float*)d_out;

    k_zero_cnt<<<1, 32>>>();
    k_router<<<NTOK, 128>>>(x, gw, sgw);

    dim3 g1(SHARED_FF / 64, NTOK / 64);
    k_shared_gemm1<<<g1, 256>>>(x, swg, swu);

    dim3 g2(HIDDEN / 64, NTOK / 64);
    k_shared_gemm2<<<g2, 256>>>(swd, out);

    dim3 g3(MOE_FF / 64, NTOK / 64, NE);
    k_expert_gemm1<<<g3, 256>>>(x, wgu);

    dim3 g4(HIDDEN / 64, NTOK / 64, NE);
    k_expert_gemm2<<<g4, 256>>>(wdn);

    k_combine<<<(NTOK * HIDDEN / 4) / 256, 256>>>(out);
}